// round 3
// baseline (speedup 1.0000x reference)
#include <cuda_runtime.h>

#define NQ    4
#define CIN   64
#define HH    64
#define WW    64
#define OUTC  128
#define TH    8
#define TW    16
#define NTHR  128
#define HALO_H (TH + 2)
#define HALO_W (TW + 2)
#define HALO_N (HALO_H * HALO_W)   // 180

// Fixed gate matrices: [0..31] = U3 per wire, [32..63] = CU3 per wire.
__device__ float g_gates[64];
// Conv weights pre-packed for f32x2 channel-pair accumulation:
// index ((s*9+tap)*4+p)*2+h  ->  (w[c0][oa], w[c1][oa], w[c0][ob], w[c1][ob])
// with c0 = s*8+2p, c1 = c0+1, oa = 2h, ob = 2h+1.
__device__ float4 g_wpack[576];

#define FMA2(acc, a, b) \
    asm("fma.rn.f32x2 %0, %1, %2, %0;" : "+l"(acc) : "l"(a), "l"(b))

__global__ void init_kernel(const float* __restrict__ fc1w,
                            const float* __restrict__ u3p,
                            const float* __restrict__ cu3p)
{
    int i = threadIdx.x;
    if (i < 8) {
        const float* p = (i < 4) ? (u3p + i * 3) : (cu3p + (i - 4) * 3);
        float th = p[0], ph = p[1], la = p[2];
        float st, ct;   sincosf(0.5f * th, &st, &ct);
        float sl, cl;   sincosf(la, &sl, &cl);
        float sp, cp;   sincosf(ph, &sp, &cp);
        float spl, cpl; sincosf(ph + la, &spl, &cpl);
        float* o = g_gates + i * 8;
        o[0] = ct;        o[1] = 0.f;
        o[2] = -cl * st;  o[3] = -sl * st;
        o[4] = cp * st;   o[5] = sp * st;
        o[6] = cpl * ct;  o[7] = spl * ct;
    }
    // i indexes the 576 packed float4 entries: h=i&1, p=(i>>1)&3, tap=(i>>3)%9, s=i/72
    {
        int h   = i & 1;
        int p   = (i >> 1) & 3;
        int tap = (i >> 3) % 9;
        int s   = i / 72;
        int c0  = s * 8 + 2 * p;
        int c1  = c0 + 1;
        int oa  = 2 * h, ob = 2 * h + 1;
        g_wpack[i] = make_float4(fc1w[oa * 576 + c0 * 9 + tap],
                                 fc1w[oa * 576 + c1 * 9 + tap],
                                 fc1w[ob * 576 + c0 * 9 + tap],
                                 fc1w[ob * 576 + c1 * 9 + tap]);
    }
}

__global__ __launch_bounds__(NTHR, 4)
void qconv_kernel(const float* __restrict__ x,     // (16,64,64,64)
                  const float* __restrict__ fc1b,  // (4,)
                  const float* __restrict__ fcw,   // (128,4)
                  const float* __restrict__ fcb,   // (128,)
                  float* __restrict__ out)         // (16,4096,128) flat
{
    __shared__ float4 wq[576];            // packed weights (f32x2 pairs)
    __shared__ float4 xs4[2][2][HALO_N];  // [buf][chan-group][pos] 4 channels/float4
    __shared__ float4 ez[NTHR];

    const int t  = threadIdx.x;
    const int b  = blockIdx.z;
    const int h0 = blockIdx.y * TH;
    const int w0 = blockIdx.x * TW;

    #pragma unroll
    for (int f = t; f < 576; f += NTHR)
        wq[f] = g_wpack[f];

    const int ty = t >> 4;   // 0..7
    const int tx = t & 15;   // 0..15
    const int by = h0 - 1, bx = w0 - 1;

    // Channel-invariant halo staging: predicate + clamped base, computed ONCE.
    const int s_r0 = t / HALO_W, s_c0 = t - s_r0 * HALO_W;
    const int idx1 = t + NTHR;
    const int s_r1 = idx1 / HALO_W, s_c1 = idx1 - s_r1 * HALO_W;
    const bool has1 = (idx1 < HALO_N);

    int gy0 = by + s_r0, gx0 = bx + s_c0;
    const bool valid0 = (unsigned)gy0 < (unsigned)HH && (unsigned)gx0 < (unsigned)WW;
    int gy1 = by + s_r1, gx1 = bx + s_c1;
    const bool valid1 = has1 && (unsigned)gy1 < (unsigned)HH && (unsigned)gx1 < (unsigned)WW;

    const float* xb0 = x + ((size_t)b * CIN) * (HH * WW);
    const float* cur0 = xb0 + (valid0 ? gy0 * WW + gx0 : 0);
    const float* cur1 = xb0 + (valid1 ? gy1 * WW + gx1 : 0);

    float v0[8], v1[8];
    #pragma unroll
    for (int k = 0; k < 8; ++k) v0[k] = valid0 ? cur0[k * (HH * WW)] : 0.f;
    #pragma unroll
    for (int k = 0; k < 8; ++k) v1[k] = valid1 ? cur1[k * (HH * WW)] : 0.f;
    cur0 += 8 * HH * WW; cur1 += 8 * HH * WW;

    xs4[0][0][t] = make_float4(v0[0], v0[1], v0[2], v0[3]);
    xs4[0][1][t] = make_float4(v0[4], v0[5], v0[6], v0[7]);
    if (has1) {
        xs4[0][0][idx1] = make_float4(v1[0], v1[1], v1[2], v1[3]);
        xs4[0][1][idx1] = make_float4(v1[4], v1[5], v1[6], v1[7]);
    }
    __syncthreads();

    // Packed accumulators: acc_o = (sum over even channels, sum over odd channels)
    unsigned long long acc0, acc1, acc2, acc3;
    {
        float z = 0.f;
        float b0 = fc1b[0], b1 = fc1b[1], b2 = fc1b[2], b3 = fc1b[3];
        asm("mov.b64 %0, {%1, %2};" : "=l"(acc0) : "f"(b0), "f"(z));
        asm("mov.b64 %0, {%1, %2};" : "=l"(acc1) : "f"(b1), "f"(z));
        asm("mov.b64 %0, {%1, %2};" : "=l"(acc2) : "f"(b2), "f"(z));
        asm("mov.b64 %0, {%1, %2};" : "=l"(acc3) : "f"(b3), "f"(z));
    }

    for (int s = 0; s < 8; ++s) {
        if (s < 7) {
            #pragma unroll
            for (int k = 0; k < 8; ++k) v0[k] = valid0 ? cur0[k * (HH * WW)] : 0.f;
            #pragma unroll
            for (int k = 0; k < 8; ++k) v1[k] = valid1 ? cur1[k * (HH * WW)] : 0.f;
            cur0 += 8 * HH * WW; cur1 += 8 * HH * WW;
        }

        const ulonglong2* xg0 = (const ulonglong2*)xs4[s & 1][0];
        const ulonglong2* xg1 = (const ulonglong2*)xs4[s & 1][1];
        const ulonglong2* wp  = (const ulonglong2*)(wq + s * 72);

        #pragma unroll
        for (int di = 0; di < 3; ++di) {
            #pragma unroll
            for (int dj = 0; dj < 3; ++dj) {
                const int pos = (ty + di) * HALO_W + tx + dj;
                const int tap = di * 3 + dj;
                ulonglong2 xa = xg0[pos];   // pairs (c0,c1), (c2,c3)
                ulonglong2 xb4 = xg1[pos];  // pairs (c4,c5), (c6,c7)
                ulonglong2 wA, wB;
                // p = 0
                wA = wp[tap * 8 + 0];  wB = wp[tap * 8 + 1];
                FMA2(acc0, xa.x, wA.x); FMA2(acc1, xa.x, wA.y);
                FMA2(acc2, xa.x, wB.x); FMA2(acc3, xa.x, wB.y);
                // p = 1
                wA = wp[tap * 8 + 2];  wB = wp[tap * 8 + 3];
                FMA2(acc0, xa.y, wA.x); FMA2(acc1, xa.y, wA.y);
                FMA2(acc2, xa.y, wB.x); FMA2(acc3, xa.y, wB.y);
                // p = 2
                wA = wp[tap * 8 + 4];  wB = wp[tap * 8 + 5];
                FMA2(acc0, xb4.x, wA.x); FMA2(acc1, xb4.x, wA.y);
                FMA2(acc2, xb4.x, wB.x); FMA2(acc3, xb4.x, wB.y);
                // p = 3
                wA = wp[tap * 8 + 6];  wB = wp[tap * 8 + 7];
                FMA2(acc0, xb4.y, wA.x); FMA2(acc1, xb4.y, wA.y);
                FMA2(acc2, xb4.y, wB.x); FMA2(acc3, xb4.y, wB.y);
            }
        }
        __syncthreads();
        if (s < 7) {
            float4* d0 = xs4[(s + 1) & 1][0];
            float4* d1 = xs4[(s + 1) & 1][1];
            d0[t] = make_float4(v0[0], v0[1], v0[2], v0[3]);
            d1[t] = make_float4(v0[4], v0[5], v0[6], v0[7]);
            if (has1) {
                d0[idx1] = make_float4(v1[0], v1[1], v1[2], v1[3]);
                d1[idx1] = make_float4(v1[4], v1[5], v1[6], v1[7]);
            }
            __syncthreads();
        }
    }

    // Reduce packed accumulators -> 4 angles
    float a0, a1, a2, a3;
    {
        float lo, hi;
        asm("mov.b64 {%0, %1}, %2;" : "=f"(lo), "=f"(hi) : "l"(acc0)); a0 = lo + hi;
        asm("mov.b64 {%0, %1}, %2;" : "=f"(lo), "=f"(hi) : "l"(acc1)); a1 = lo + hi;
        asm("mov.b64 {%0, %1}, %2;" : "=f"(lo), "=f"(hi) : "l"(acc2)); a2 = lo + hi;
        asm("mov.b64 {%0, %1}, %2;" : "=f"(lo), "=f"(hi) : "l"(acc3)); a3 = lo + hi;
    }

    // ---------------- quantum circuit (per pixel, in registers) ----------------
    float S[NQ][4];
    float angs[NQ] = {a0, a1, a2, a3};
    #pragma unroll
    for (int q = 0; q < NQ; ++q) {
        float st, ct;
        __sincosf(0.5f * angs[q], &st, &ct);
        const float* m = g_gates + q * 8;
        S[q][0] = m[0] * ct + m[2] * st;
        S[q][1] = m[1] * ct + m[3] * st;
        S[q][2] = m[4] * ct + m[6] * st;
        S[q][3] = m[5] * ct + m[7] * st;
    }

    float q01r[4], q01i[4], q23r[4], q23i[4];
    #pragma unroll
    for (int i0 = 0; i0 < 2; ++i0)
        #pragma unroll
        for (int i1 = 0; i1 < 2; ++i1) {
            float xr = S[0][i0 * 2], xi = S[0][i0 * 2 + 1];
            float yr = S[1][i1 * 2], yi = S[1][i1 * 2 + 1];
            q01r[i0 * 2 + i1] = xr * yr - xi * yi;
            q01i[i0 * 2 + i1] = xr * yi + xi * yr;
            xr = S[2][i0 * 2]; xi = S[2][i0 * 2 + 1];
            yr = S[3][i1 * 2]; yi = S[3][i1 * 2 + 1];
            q23r[i0 * 2 + i1] = xr * yr - xi * yi;
            q23i[i0 * 2 + i1] = xr * yi + xi * yr;
        }

    float pr[16], pi[16];
    #pragma unroll
    for (int u = 0; u < 4; ++u)
        #pragma unroll
        for (int v = 0; v < 4; ++v) {
            pr[u * 4 + v] = q01r[u] * q23r[v] - q01i[u] * q23i[v];
            pi[u * 4 + v] = q01r[u] * q23i[v] + q01i[u] * q23r[v];
        }

    #pragma unroll
    for (int g = 0; g < 4; ++g) {
        const float* U = g_gates + 32 + g * 8;
        float u00r = U[0], u00i = U[1], u01r = U[2], u01i = U[3];
        float u10r = U[4], u10i = U[5], u11r = U[6], u11i = U[7];
        const int bc = 8 >> g;
        const int bt = 8 >> ((g + 1) & 3);
        #pragma unroll
        for (int i = 0; i < 16; ++i) {
            if ((i & bc) && !(i & bt)) {
                const int j = i | bt;
                float x0r = pr[i], x0i = pi[i], x1r = pr[j], x1i = pi[j];
                pr[i] = u00r * x0r - u00i * x0i + u01r * x1r - u01i * x1i;
                pi[i] = u00r * x0i + u00i * x0r + u01r * x1i + u01i * x1r;
                pr[j] = u10r * x0r - u10i * x0i + u11r * x1r - u11i * x1i;
                pi[j] = u10r * x0i + u10i * x0r + u11r * x1i + u11i * x1r;
            }
        }
    }

    float e0 = 0.f, e1 = 0.f, e2 = 0.f, e3 = 0.f;
    #pragma unroll
    for (int i = 0; i < 16; ++i) {
        float pp = pr[i] * pr[i] + pi[i] * pi[i];
        e0 += (i & 8) ? -pp : pp;
        e1 += (i & 4) ? -pp : pp;
        e2 += (i & 2) ? -pp : pp;
        e3 += (i & 1) ? -pp : pp;
    }

    ez[t] = make_float4(e0, e1, e2, e3);
    __syncthreads();

    // ---------------- coalesced FC epilogue ----------------
    const int lane = t & 31;
    const int wi   = t >> 5;
    const float4* fw4 = (const float4*)fcw;
    float4 wr0 = fw4[4 * lane + 0];
    float4 wr1 = fw4[4 * lane + 1];
    float4 wr2 = fw4[4 * lane + 2];
    float4 wr3 = fw4[4 * lane + 3];
    float4 bb4 = ((const float4*)fcb)[lane];

    float4* ob = (float4*)out + (size_t)b * 4096 * 32;
    #pragma unroll 4
    for (int j = 0; j < 32; ++j) {
        const int lp = wi * 32 + j;
        float4 e = ez[lp];
        const int py = h0 + (lp >> 4);
        const int px = w0 + (lp & 15);
        const int p  = py * WW + px;
        float4 o;
        o.x = bb4.x + wr0.x * e.x + wr0.y * e.y + wr0.z * e.z + wr0.w * e.w;
        o.y = bb4.y + wr1.x * e.x + wr1.y * e.y + wr1.z * e.z + wr1.w * e.w;
        o.z = bb4.z + wr2.x * e.x + wr2.y * e.y + wr2.z * e.z + wr2.w * e.w;
        o.w = bb4.w + wr3.x * e.x + wr3.y * e.y + wr3.z * e.z + wr3.w * e.w;
        ob[(size_t)p * 32 + lane] = o;
    }
}

extern "C" void kernel_launch(void* const* d_in, const int* in_sizes, int n_in,
                              void* d_out, int out_size)
{
    (void)in_sizes; (void)n_in; (void)out_size;
    const float* x    = (const float*)d_in[0];
    const float* fc1w = (const float*)d_in[1];
    const float* fc1b = (const float*)d_in[2];
    const float* u3p  = (const float*)d_in[3];
    const float* cu3p = (const float*)d_in[4];
    const float* fcw  = (const float*)d_in[5];
    const float* fcb  = (const float*)d_in[6];
    float* out = (float*)d_out;

    init_kernel<<<1, 576>>>(fc1w, u3p, cu3p);
    dim3 grid(WW / TW, HH / TH, 16);
    qconv_kernel<<<grid, NTHR>>>(x, fc1b, fcw, fcb, out);
}

// round 4
// speedup vs baseline: 1.2750x; 1.2750x over previous
#include <cuda_runtime.h>

#define NQ    4
#define CIN   64
#define HH    64
#define WW    64
#define OUTC  128
#define TH    16
#define TW    16
#define NTHR  128
#define HALO_H (TH + 2)
#define HALO_W (TW + 2)
#define HALO_N (HALO_H * HALO_W)   // 324

// Fixed gate matrices: [0..31] = U3 per wire, [32..63] = CU3 per wire.
__device__ float g_gates[64];
// Conv weights pre-packed for f32x2 channel-pair accumulation:
// index ((s*9+tap)*4+p)*2+h  ->  (w[c0][oa], w[c1][oa], w[c0][ob], w[c1][ob])
// with c0 = s*8+2p, c1 = c0+1, oa = 2h, ob = 2h+1.
__device__ float4 g_wpack[576];

#define FMA2(acc, a, b) \
    asm("fma.rn.f32x2 %0, %1, %2, %0;" : "+l"(acc) : "l"(a), "l"(b))

__global__ void init_kernel(const float* __restrict__ fc1w,
                            const float* __restrict__ u3p,
                            const float* __restrict__ cu3p)
{
    int i = threadIdx.x;
    if (i < 8) {
        const float* p = (i < 4) ? (u3p + i * 3) : (cu3p + (i - 4) * 3);
        float th = p[0], ph = p[1], la = p[2];
        float st, ct;   sincosf(0.5f * th, &st, &ct);
        float sl, cl;   sincosf(la, &sl, &cl);
        float sp, cp;   sincosf(ph, &sp, &cp);
        float spl, cpl; sincosf(ph + la, &spl, &cpl);
        float* o = g_gates + i * 8;
        o[0] = ct;        o[1] = 0.f;
        o[2] = -cl * st;  o[3] = -sl * st;
        o[4] = cp * st;   o[5] = sp * st;
        o[6] = cpl * ct;  o[7] = spl * ct;
    }
    {
        int h   = i & 1;
        int p   = (i >> 1) & 3;
        int tap = (i >> 3) % 9;
        int s   = i / 72;
        int c0  = s * 8 + 2 * p;
        int c1  = c0 + 1;
        int oa  = 2 * h, ob = 2 * h + 1;
        g_wpack[i] = make_float4(fc1w[oa * 576 + c0 * 9 + tap],
                                 fc1w[oa * 576 + c1 * 9 + tap],
                                 fc1w[ob * 576 + c0 * 9 + tap],
                                 fc1w[ob * 576 + c1 * 9 + tap]);
    }
}

// Full 4-qubit circuit from the 4 angles -> <Z> per wire.
__device__ __forceinline__ float4 quantum_ez(float a0, float a1, float a2, float a3)
{
    float S[NQ][4];
    float angs[NQ] = {a0, a1, a2, a3};
    #pragma unroll
    for (int q = 0; q < NQ; ++q) {
        float st, ct;
        __sincosf(0.5f * angs[q], &st, &ct);
        const float* m = g_gates + q * 8;
        S[q][0] = m[0] * ct + m[2] * st;
        S[q][1] = m[1] * ct + m[3] * st;
        S[q][2] = m[4] * ct + m[6] * st;
        S[q][3] = m[5] * ct + m[7] * st;
    }

    float q01r[4], q01i[4], q23r[4], q23i[4];
    #pragma unroll
    for (int i0 = 0; i0 < 2; ++i0)
        #pragma unroll
        for (int i1 = 0; i1 < 2; ++i1) {
            float xr = S[0][i0 * 2], xi = S[0][i0 * 2 + 1];
            float yr = S[1][i1 * 2], yi = S[1][i1 * 2 + 1];
            q01r[i0 * 2 + i1] = xr * yr - xi * yi;
            q01i[i0 * 2 + i1] = xr * yi + xi * yr;
            xr = S[2][i0 * 2]; xi = S[2][i0 * 2 + 1];
            yr = S[3][i1 * 2]; yi = S[3][i1 * 2 + 1];
            q23r[i0 * 2 + i1] = xr * yr - xi * yi;
            q23i[i0 * 2 + i1] = xr * yi + xi * yr;
        }

    float pr[16], pi[16];
    #pragma unroll
    for (int u = 0; u < 4; ++u)
        #pragma unroll
        for (int v = 0; v < 4; ++v) {
            pr[u * 4 + v] = q01r[u] * q23r[v] - q01i[u] * q23i[v];
            pi[u * 4 + v] = q01r[u] * q23i[v] + q01i[u] * q23r[v];
        }

    #pragma unroll
    for (int g = 0; g < 4; ++g) {
        const float* U = g_gates + 32 + g * 8;
        float u00r = U[0], u00i = U[1], u01r = U[2], u01i = U[3];
        float u10r = U[4], u10i = U[5], u11r = U[6], u11i = U[7];
        const int bc = 8 >> g;
        const int bt = 8 >> ((g + 1) & 3);
        #pragma unroll
        for (int i = 0; i < 16; ++i) {
            if ((i & bc) && !(i & bt)) {
                const int j = i | bt;
                float x0r = pr[i], x0i = pi[i], x1r = pr[j], x1i = pi[j];
                pr[i] = u00r * x0r - u00i * x0i + u01r * x1r - u01i * x1i;
                pi[i] = u00r * x0i + u00i * x0r + u01r * x1i + u01i * x1r;
                pr[j] = u10r * x0r - u10i * x0i + u11r * x1r - u11i * x1i;
                pi[j] = u10r * x0i + u10i * x0r + u11r * x1i + u11i * x1r;
            }
        }
    }

    float e0 = 0.f, e1 = 0.f, e2 = 0.f, e3 = 0.f;
    #pragma unroll
    for (int i = 0; i < 16; ++i) {
        float pp = pr[i] * pr[i] + pi[i] * pi[i];
        e0 += (i & 8) ? -pp : pp;
        e1 += (i & 4) ? -pp : pp;
        e2 += (i & 2) ? -pp : pp;
        e3 += (i & 1) ? -pp : pp;
    }
    return make_float4(e0, e1, e2, e3);
}

__global__ __launch_bounds__(NTHR, 2)
void qconv_kernel(const float* __restrict__ x,     // (16,64,64,64)
                  const float* __restrict__ fc1b,  // (4,)
                  const float* __restrict__ fcw,   // (128,4)
                  const float* __restrict__ fcb,   // (128,)
                  float* __restrict__ out)         // (16,4096,128) flat
{
    __shared__ float4 wq[576];            // packed weights (f32x2 pairs)
    __shared__ float4 xs4[2][2][HALO_N];  // [buf][chan-group][pos] 4 channels/float4
    __shared__ float4 ez[TH * TW];        // 256 pixels

    const int t  = threadIdx.x;
    const int b  = blockIdx.z;
    const int h0 = blockIdx.y * TH;
    const int w0 = blockIdx.x * TW;

    #pragma unroll
    for (int f = t; f < 576; f += NTHR)
        wq[f] = g_wpack[f];

    const int ty = t >> 4;   // 0..7  (handles pixel rows 2ty, 2ty+1)
    const int tx = t & 15;   // 0..15
    const int by = h0 - 1, bx = w0 - 1;

    // ---- channel-invariant halo staging: 3 slots/thread over 324 positions ----
    const int i0 = t, i1 = t + NTHR, i2 = t + 2 * NTHR;
    const bool has2 = (i2 < HALO_N);
    const int r0 = i0 / HALO_W, c0s = i0 - r0 * HALO_W;
    const int r1 = i1 / HALO_W, c1s = i1 - r1 * HALO_W;
    const int r2 = has2 ? i2 / HALO_W : 0, c2s = has2 ? (i2 - r2 * HALO_W) : 0;

    int gy, gx;
    gy = by + r0; gx = bx + c0s;
    const bool va0 = (unsigned)gy < (unsigned)HH && (unsigned)gx < (unsigned)WW;
    const float* cur0 = x + ((size_t)b * CIN) * (HH * WW) + (va0 ? gy * WW + gx : 0);
    gy = by + r1; gx = bx + c1s;
    const bool va1 = (unsigned)gy < (unsigned)HH && (unsigned)gx < (unsigned)WW;
    const float* cur1 = x + ((size_t)b * CIN) * (HH * WW) + (va1 ? gy * WW + gx : 0);
    gy = by + r2; gx = bx + c2s;
    const bool va2 = has2 && (unsigned)gy < (unsigned)HH && (unsigned)gx < (unsigned)WW;
    const float* cur2 = x + ((size_t)b * CIN) * (HH * WW) + (va2 ? gy * WW + gx : 0);

    float v0[8], v1[8], v2[8];
    #pragma unroll
    for (int k = 0; k < 8; ++k) v0[k] = va0 ? cur0[k * (HH * WW)] : 0.f;
    #pragma unroll
    for (int k = 0; k < 8; ++k) v1[k] = va1 ? cur1[k * (HH * WW)] : 0.f;
    #pragma unroll
    for (int k = 0; k < 8; ++k) v2[k] = va2 ? cur2[k * (HH * WW)] : 0.f;
    cur0 += 8 * HH * WW; cur1 += 8 * HH * WW; cur2 += 8 * HH * WW;

    xs4[0][0][i0] = make_float4(v0[0], v0[1], v0[2], v0[3]);
    xs4[0][1][i0] = make_float4(v0[4], v0[5], v0[6], v0[7]);
    xs4[0][0][i1] = make_float4(v1[0], v1[1], v1[2], v1[3]);
    xs4[0][1][i1] = make_float4(v1[4], v1[5], v1[6], v1[7]);
    if (has2) {
        xs4[0][0][i2] = make_float4(v2[0], v2[1], v2[2], v2[3]);
        xs4[0][1][i2] = make_float4(v2[4], v2[5], v2[6], v2[7]);
    }
    __syncthreads();

    // 8 packed accumulators: A = pixel row 2ty, B = pixel row 2ty+1.
    unsigned long long A0, A1, A2, A3, B0, B1, B2, B3;
    {
        float z = 0.f;
        float b0 = fc1b[0], b1 = fc1b[1], b2 = fc1b[2], b3 = fc1b[3];
        asm("mov.b64 %0, {%1, %2};" : "=l"(A0) : "f"(b0), "f"(z));
        asm("mov.b64 %0, {%1, %2};" : "=l"(A1) : "f"(b1), "f"(z));
        asm("mov.b64 %0, {%1, %2};" : "=l"(A2) : "f"(b2), "f"(z));
        asm("mov.b64 %0, {%1, %2};" : "=l"(A3) : "f"(b3), "f"(z));
        asm("mov.b64 %0, {%1, %2};" : "=l"(B0) : "f"(b0), "f"(z));
        asm("mov.b64 %0, {%1, %2};" : "=l"(B1) : "f"(b1), "f"(z));
        asm("mov.b64 %0, {%1, %2};" : "=l"(B2) : "f"(b2), "f"(z));
        asm("mov.b64 %0, {%1, %2};" : "=l"(B3) : "f"(b3), "f"(z));
    }

    for (int s = 0; s < 8; ++s) {
        if (s < 7) {
            #pragma unroll
            for (int k = 0; k < 8; ++k) v0[k] = va0 ? cur0[k * (HH * WW)] : 0.f;
            #pragma unroll
            for (int k = 0; k < 8; ++k) v1[k] = va1 ? cur1[k * (HH * WW)] : 0.f;
            #pragma unroll
            for (int k = 0; k < 8; ++k) v2[k] = va2 ? cur2[k * (HH * WW)] : 0.f;
            cur0 += 8 * HH * WW; cur1 += 8 * HH * WW; cur2 += 8 * HH * WW;
        }

        const ulonglong2* xg0 = (const ulonglong2*)xs4[s & 1][0];
        const ulonglong2* xg1 = (const ulonglong2*)xs4[s & 1][1];
        const ulonglong2* wp  = (const ulonglong2*)(wq + s * 72);

        #pragma unroll
        for (int dj = 0; dj < 3; ++dj) {
            // 4 halo rows covering both pixels' tap windows at column tx+dj.
            ulonglong2 xlo[4], xhi[4];
            #pragma unroll
            for (int r = 0; r < 4; ++r) {
                const int pos = (2 * ty + r) * HALO_W + tx + dj;
                xlo[r] = xg0[pos];
                xhi[r] = xg1[pos];
            }
            #pragma unroll
            for (int di = 0; di < 3; ++di) {
                const ulonglong2* wt = wp + (di * 3 + dj) * 8;
                ulonglong2 w0 = wt[0], w1 = wt[1], w2 = wt[2], w3 = wt[3];
                ulonglong2 w4 = wt[4], w5 = wt[5], w6 = wt[6], w7 = wt[7];
                // pixel row 2ty uses halo row di; row 2ty+1 uses di+1.
                FMA2(A0, xlo[di].x, w0.x); FMA2(A1, xlo[di].x, w0.y);
                FMA2(A2, xlo[di].x, w1.x); FMA2(A3, xlo[di].x, w1.y);
                FMA2(B0, xlo[di+1].x, w0.x); FMA2(B1, xlo[di+1].x, w0.y);
                FMA2(B2, xlo[di+1].x, w1.x); FMA2(B3, xlo[di+1].x, w1.y);
                FMA2(A0, xlo[di].y, w2.x); FMA2(A1, xlo[di].y, w2.y);
                FMA2(A2, xlo[di].y, w3.x); FMA2(A3, xlo[di].y, w3.y);
                FMA2(B0, xlo[di+1].y, w2.x); FMA2(B1, xlo[di+1].y, w2.y);
                FMA2(B2, xlo[di+1].y, w3.x); FMA2(B3, xlo[di+1].y, w3.y);
                FMA2(A0, xhi[di].x, w4.x); FMA2(A1, xhi[di].x, w4.y);
                FMA2(A2, xhi[di].x, w5.x); FMA2(A3, xhi[di].x, w5.y);
                FMA2(B0, xhi[di+1].x, w4.x); FMA2(B1, xhi[di+1].x, w4.y);
                FMA2(B2, xhi[di+1].x, w5.x); FMA2(B3, xhi[di+1].x, w5.y);
                FMA2(A0, xhi[di].y, w6.x); FMA2(A1, xhi[di].y, w6.y);
                FMA2(A2, xhi[di].y, w7.x); FMA2(A3, xhi[di].y, w7.y);
                FMA2(B0, xhi[di+1].y, w6.x); FMA2(B1, xhi[di+1].y, w6.y);
                FMA2(B2, xhi[di+1].y, w7.x); FMA2(B3, xhi[di+1].y, w7.y);
            }
        }
        __syncthreads();
        if (s < 7) {
            float4* d0 = xs4[(s + 1) & 1][0];
            float4* d1 = xs4[(s + 1) & 1][1];
            d0[i0] = make_float4(v0[0], v0[1], v0[2], v0[3]);
            d1[i0] = make_float4(v0[4], v0[5], v0[6], v0[7]);
            d0[i1] = make_float4(v1[0], v1[1], v1[2], v1[3]);
            d1[i1] = make_float4(v1[4], v1[5], v1[6], v1[7]);
            if (has2) {
                d0[i2] = make_float4(v2[0], v2[1], v2[2], v2[3]);
                d1[i2] = make_float4(v2[4], v2[5], v2[6], v2[7]);
            }
            __syncthreads();
        }
    }

    // Reduce packed accumulators -> angles, run circuit for both pixels.
    {
        float lo, hi, a0, a1, a2, a3;
        asm("mov.b64 {%0, %1}, %2;" : "=f"(lo), "=f"(hi) : "l"(A0)); a0 = lo + hi;
        asm("mov.b64 {%0, %1}, %2;" : "=f"(lo), "=f"(hi) : "l"(A1)); a1 = lo + hi;
        asm("mov.b64 {%0, %1}, %2;" : "=f"(lo), "=f"(hi) : "l"(A2)); a2 = lo + hi;
        asm("mov.b64 {%0, %1}, %2;" : "=f"(lo), "=f"(hi) : "l"(A3)); a3 = lo + hi;
        ez[(2 * ty) * TW + tx] = quantum_ez(a0, a1, a2, a3);
        asm("mov.b64 {%0, %1}, %2;" : "=f"(lo), "=f"(hi) : "l"(B0)); a0 = lo + hi;
        asm("mov.b64 {%0, %1}, %2;" : "=f"(lo), "=f"(hi) : "l"(B1)); a1 = lo + hi;
        asm("mov.b64 {%0, %1}, %2;" : "=f"(lo), "=f"(hi) : "l"(B2)); a2 = lo + hi;
        asm("mov.b64 {%0, %1}, %2;" : "=f"(lo), "=f"(hi) : "l"(B3)); a3 = lo + hi;
        ez[(2 * ty + 1) * TW + tx] = quantum_ez(a0, a1, a2, a3);
    }
    __syncthreads();

    // ---------------- coalesced FC epilogue ----------------
    // Warp wi handles pixels wi*64 .. wi*64+63; lane k owns channels 4k..4k+3,
    // so each pixel's 128 outputs are one contiguous 512B warp burst.
    const int lane = t & 31;
    const int wi   = t >> 5;
    const float4* fw4 = (const float4*)fcw;
    float4 wr0 = fw4[4 * lane + 0];
    float4 wr1 = fw4[4 * lane + 1];
    float4 wr2 = fw4[4 * lane + 2];
    float4 wr3 = fw4[4 * lane + 3];
    float4 bb4 = ((const float4*)fcb)[lane];

    float4* ob = (float4*)out + (size_t)b * 4096 * 32;
    #pragma unroll 4
    for (int j = 0; j < 64; ++j) {
        const int lp = wi * 64 + j;
        float4 e = ez[lp];
        const int py = h0 + (lp >> 4);
        const int px = w0 + (lp & 15);
        const int p  = py * WW + px;
        float4 o;
        o.x = bb4.x + wr0.x * e.x + wr0.y * e.y + wr0.z * e.z + wr0.w * e.w;
        o.y = bb4.y + wr1.x * e.x + wr1.y * e.y + wr1.z * e.z + wr1.w * e.w;
        o.z = bb4.z + wr2.x * e.x + wr2.y * e.y + wr2.z * e.z + wr2.w * e.w;
        o.w = bb4.w + wr3.x * e.x + wr3.y * e.y + wr3.z * e.z + wr3.w * e.w;
        ob[(size_t)p * 32 + lane] = o;
    }
}

extern "C" void kernel_launch(void* const* d_in, const int* in_sizes, int n_in,
                              void* d_out, int out_size)
{
    (void)in_sizes; (void)n_in; (void)out_size;
    const float* x    = (const float*)d_in[0];
    const float* fc1w = (const float*)d_in[1];
    const float* fc1b = (const float*)d_in[2];
    const float* u3p  = (const float*)d_in[3];
    const float* cu3p = (const float*)d_in[4];
    const float* fcw  = (const float*)d_in[5];
    const float* fcb  = (const float*)d_in[6];
    float* out = (float*)d_out;

    init_kernel<<<1, 576>>>(fc1w, u3p, cu3p);
    dim3 grid(WW / TW, HH / TH, 16);
    qconv_kernel<<<grid, NTHR>>>(x, fc1b, fcw, fcb, out);
}